// round 4
// baseline (speedup 1.0000x reference)
#include <cuda_runtime.h>
#include <cstdint>
#include <math.h>

#define T_TOK 4096
#define EMB   1024
#define HID   2816
#define NE    8
#define NPAIR (T_TOK * 2)

// ---------------- device scratch ---------------------------------------------
__device__ int   g_counts[NE];
__device__ int   g_offsets[NE + 1];
__device__ int   g_cursor[NE];
__device__ int   g_tok_e[T_TOK][2];
__device__ float g_tok_p[T_TOK][2];
__device__ int   g_pair_token[NPAIR];
__device__ float g_pair_gate[NPAIR];
__device__ int   g_pair_slot[NPAIR];
__device__ float g_hbuf[(size_t)NPAIR * HID];        // 92 MB (tf32-rounded)
__device__ float g_contrib[2][T_TOK][EMB];           // 32 MB
__device__ float g_rx [(size_t)T_TOK * EMB];         // 16 MB  tf32-rounded x
__device__ float g_rw1[(size_t)NE * EMB * HID];      // 92 MB  tf32-rounded w1
__device__ float g_rw3[(size_t)NE * EMB * HID];      // 92 MB  tf32-rounded w3
__device__ float g_rw2[(size_t)NE * HID * EMB];      // 92 MB  tf32-rounded w2

// ---------------- helpers ----------------------------------------------------
__device__ __forceinline__ float to_tf32(float x) {
    uint32_t u;
    asm("cvt.rna.tf32.f32 %0, %1;" : "=r"(u) : "f"(x));
    return __uint_as_float(u);
}

__device__ __forceinline__ void mma_tf32(float c[4], const uint32_t a[4], const uint32_t b[2]) {
    asm volatile(
        "mma.sync.aligned.m16n8k8.row.col.f32.tf32.tf32.f32 "
        "{%0,%1,%2,%3}, {%4,%5,%6,%7}, {%8,%9}, {%0,%1,%2,%3};\n"
        : "+f"(c[0]), "+f"(c[1]), "+f"(c[2]), "+f"(c[3])
        : "r"(a[0]), "r"(a[1]), "r"(a[2]), "r"(a[3]),
          "r"(b[0]), "r"(b[1]));
}

__device__ __forceinline__ void cp16(float* sdst, const float* gsrc, bool p) {
    uint32_t s = (uint32_t)__cvta_generic_to_shared(sdst);
    asm volatile("cp.async.cg.shared.global [%0], [%1], 16, %2;\n"
                 :: "r"(s), "l"(gsrc), "r"(p ? 16 : 0));
}
#define CP_COMMIT asm volatile("cp.async.commit_group;\n" ::: "memory")
#define CP_WAIT1  asm volatile("cp.async.wait_group 1;\n" ::: "memory")

// ---------------- preround kernels -------------------------------------------
__global__ void preround_w_kernel(const float4* __restrict__ w1,
                                  const float4* __restrict__ w3,
                                  const float4* __restrict__ w2) {
    const int n4 = NE * EMB * HID / 4;
    float4* d1 = (float4*)g_rw1;
    float4* d3 = (float4*)g_rw3;
    float4* d2 = (float4*)g_rw2;
    int stride = gridDim.x * blockDim.x;
    for (int i = blockIdx.x * blockDim.x + threadIdx.x; i < n4; i += stride) {
        float4 a = w1[i], b = w3[i], c = w2[i];
        d1[i] = make_float4(to_tf32(a.x), to_tf32(a.y), to_tf32(a.z), to_tf32(a.w));
        d3[i] = make_float4(to_tf32(b.x), to_tf32(b.y), to_tf32(b.z), to_tf32(b.w));
        d2[i] = make_float4(to_tf32(c.x), to_tf32(c.y), to_tf32(c.z), to_tf32(c.w));
    }
}

__global__ void preround_x_kernel(const float4* __restrict__ x) {
    // also zero the routing metadata (fused so ffn1 is the 6th launch for ncu)
    if (blockIdx.x == 0 && threadIdx.x < NE) {
        g_counts[threadIdx.x] = 0; g_cursor[threadIdx.x] = 0;
    }
    const int n4 = T_TOK * EMB / 4;
    float4* dx = (float4*)g_rx;
    int stride = gridDim.x * blockDim.x;
    for (int i = blockIdx.x * blockDim.x + threadIdx.x; i < n4; i += stride) {
        float4 a = x[i];
        dx[i] = make_float4(to_tf32(a.x), to_tf32(a.y), to_tf32(a.z), to_tf32(a.w));
    }
}

// ---------------- router (one warp per token) --------------------------------
__global__ void router_kernel(const float* __restrict__ x, const float* __restrict__ wr) {
    int gw   = (blockIdx.x * blockDim.x + threadIdx.x) >> 5;
    int lane = threadIdx.x & 31;
    if (gw >= T_TOK) return;
    const float* xr = x + (size_t)gw * EMB;
    float acc[NE];
#pragma unroll
    for (int e = 0; e < NE; e++) acc[e] = 0.f;
    for (int k = lane; k < EMB; k += 32) {
        float  xv = xr[k];
        float4 wa = *(const float4*)(wr + k * NE);
        float4 wb = *(const float4*)(wr + k * NE + 4);
        acc[0] += xv * wa.x; acc[1] += xv * wa.y; acc[2] += xv * wa.z; acc[3] += xv * wa.w;
        acc[4] += xv * wb.x; acc[5] += xv * wb.y; acc[6] += xv * wb.z; acc[7] += xv * wb.w;
    }
#pragma unroll
    for (int e = 0; e < NE; e++)
#pragma unroll
        for (int o = 16; o > 0; o >>= 1) acc[e] += __shfl_xor_sync(0xffffffffu, acc[e], o);
    if (lane == 0) {
        int i0 = 0; float v0 = acc[0];
#pragma unroll
        for (int e = 1; e < NE; e++) if (acc[e] > v0) { v0 = acc[e]; i0 = e; }
        int i1 = -1; float v1 = -1e30f;
#pragma unroll
        for (int e = 0; e < NE; e++) if (e != i0 && acc[e] > v1) { v1 = acc[e]; i1 = e; }
        float p1 = 1.f / (1.f + expf(v0 - v1));
        float p0 = 1.f - p1;
        g_tok_e[gw][0] = i0; g_tok_e[gw][1] = i1;
        g_tok_p[gw][0] = p0; g_tok_p[gw][1] = p1;
        atomicAdd(&g_counts[i0], 1);
        atomicAdd(&g_counts[i1], 1);
    }
}

__global__ void offsets_kernel() {
    if (threadIdx.x == 0) {
        int s = 0;
        for (int e = 0; e < NE; e++) { g_offsets[e] = s; s += g_counts[e]; }
        g_offsets[NE] = s;
    }
}

__global__ void scatter_kernel() {
    int i = blockIdx.x * blockDim.x + threadIdx.x;
    if (i >= NPAIR) return;
    int t = i >> 1, k = i & 1;
    int e = g_tok_e[t][k];
    int pos = g_offsets[e] + atomicAdd(&g_cursor[e], 1);
    g_pair_token[pos] = t;
    g_pair_gate[pos]  = g_tok_p[t][k];
    g_pair_slot[pos]  = k;
}

// ---------------- phase-1: grouped GEMM + SwiGLU (cp.async 2-stage) ----------
#define BM  128
#define BN1 64
#define BK  32
#define AS_STRIDE  44          /* conflict-free, 16B aligned rows */
#define BS1_STRIDE 72
#define AS_TILE  (BM * AS_STRIDE)     /* 5632 floats */
#define BS1_TILE (BK * BS1_STRIDE)    /* 2304 floats */
#define FFN1_SMEM ((2 * AS_TILE + 4 * BS1_TILE) * 4)   /* 81920 B */
#define CS1_STRIDE 72

__global__ void __launch_bounds__(256, 2) ffn1_kernel() {
    extern __shared__ float smem[];
    float* As  = smem;                       // 2 stages
    float* B1s = smem + 2 * AS_TILE;         // 2 stages
    float* B3s = B1s + 2 * BS1_TILE;

    int e = blockIdx.z, nt = blockIdx.y, mt = blockIdx.x;
    int pbeg = g_offsets[e], pend = g_offsets[e + 1];
    int m0 = pbeg + mt * BM;
    if (m0 >= pend) return;
    int mcnt = pend - m0; if (mcnt > BM) mcnt = BM;

    int tid = threadIdx.x;
    int warp = tid >> 5, lane = tid & 31;
    int wm = warp & 3, wn = warp >> 2;

    int  arow   = tid >> 1;
    bool avalid = arow < mcnt;
    int  atok   = avalid ? g_pair_token[m0 + arow] : 0;
    const float* asrc = g_rx + (size_t)atok * EMB + (tid & 1) * 16;
    const float* w1p  = g_rw1 + (size_t)e * EMB * HID + (size_t)nt * BN1;
    const float* w3p  = g_rw3 + (size_t)e * EMB * HID + (size_t)nt * BN1;

    float ch[2][4][4], cg[2][4][4];
#pragma unroll
    for (int a = 0; a < 2; a++)
#pragma unroll
        for (int b = 0; b < 4; b++)
#pragma unroll
            for (int c = 0; c < 4; c++) { ch[a][b][c] = 0.f; cg[a][b][c] = 0.f; }

    int r16 = tid >> 4, c16 = tid & 15;    // B-tile mapping: 256 threads, 2 passes

    // prologue: stage 0
    {
        float* Ab = As;
#pragma unroll
        for (int i = 0; i < 4; i++)
            cp16(Ab + arow * AS_STRIDE + (tid & 1) * 16 + i * 4, asrc + i * 4, avalid);
#pragma unroll
        for (int j = 0; j < 2; j++) {
            int r = r16 + j * 16;
            cp16(B1s + r * BS1_STRIDE + c16 * 4, w1p + (size_t)r * HID + c16 * 4, true);
            cp16(B3s + r * BS1_STRIDE + c16 * 4, w3p + (size_t)r * HID + c16 * 4, true);
        }
        CP_COMMIT;
    }

    const int NIT = EMB / BK;
    for (int it = 0; it < NIT; ++it) {
        int cur = it & 1;
        if (it + 1 < NIT) {
            int k0 = (it + 1) * BK;
            int st = cur ^ 1;
            float* Ab = As + st * AS_TILE;
#pragma unroll
            for (int i = 0; i < 4; i++)
                cp16(Ab + arow * AS_STRIDE + (tid & 1) * 16 + i * 4, asrc + k0 + i * 4, avalid);
            float* B1b = B1s + st * BS1_TILE;
            float* B3b = B3s + st * BS1_TILE;
#pragma unroll
            for (int j = 0; j < 2; j++) {
                int r = r16 + j * 16;
                cp16(B1b + r * BS1_STRIDE + c16 * 4, w1p + (size_t)(k0 + r) * HID + c16 * 4, true);
                cp16(B3b + r * BS1_STRIDE + c16 * 4, w3p + (size_t)(k0 + r) * HID + c16 * 4, true);
            }
        }
        CP_COMMIT;
        CP_WAIT1;
        __syncthreads();

        const float* Ab  = As  + cur * AS_TILE;
        const float* B1b = B1s + cur * BS1_TILE;
        const float* B3b = B3s + cur * BS1_TILE;
#pragma unroll
        for (int kk = 0; kk < BK; kk += 8) {
            uint32_t a[2][4];
            int ar  = wm * 32 + (lane >> 2);
            int acl = kk + (lane & 3);
#pragma unroll
            for (int mi = 0; mi < 2; mi++) {
                a[mi][0] = __float_as_uint(Ab[(ar + mi * 16)     * AS_STRIDE + acl]);
                a[mi][1] = __float_as_uint(Ab[(ar + mi * 16 + 8) * AS_STRIDE + acl]);
                a[mi][2] = __float_as_uint(Ab[(ar + mi * 16)     * AS_STRIDE + acl + 4]);
                a[mi][3] = __float_as_uint(Ab[(ar + mi * 16 + 8) * AS_STRIDE + acl + 4]);
            }
            int bk  = kk + (lane & 3);
            int bnb = wn * 32 + (lane >> 2);
#pragma unroll
            for (int ni = 0; ni < 4; ni++) {
                uint32_t b1[2], b3[2];
                b1[0] = __float_as_uint(B1b[bk * BS1_STRIDE + bnb + ni * 8]);
                b1[1] = __float_as_uint(B1b[(bk + 4) * BS1_STRIDE + bnb + ni * 8]);
                b3[0] = __float_as_uint(B3b[bk * BS1_STRIDE + bnb + ni * 8]);
                b3[1] = __float_as_uint(B3b[(bk + 4) * BS1_STRIDE + bnb + ni * 8]);
#pragma unroll
                for (int mi = 0; mi < 2; mi++) {
                    mma_tf32(ch[mi][ni], a[mi], b1);
                    mma_tf32(cg[mi][ni], a[mi], b3);
                }
            }
        }
        __syncthreads();
    }

    // epilogue: silu(h)*g -> smem stage -> coalesced tf32-rounded stores
    float* Cs = smem;
#pragma unroll
    for (int mi = 0; mi < 2; mi++)
#pragma unroll
        for (int ni = 0; ni < 4; ni++)
#pragma unroll
            for (int r = 0; r < 4; r++) {
                int row = wm * 32 + mi * 16 + (lane >> 2) + ((r >= 2) ? 8 : 0);
                int col = wn * 32 + ni * 8 + (lane & 3) * 2 + (r & 1);
                float h = ch[mi][ni][r], g = cg[mi][ni][r];
                Cs[row * CS1_STRIDE + col] = to_tf32((h / (1.f + expf(-h))) * g);
            }
    __syncthreads();
    {
        int row = tid >> 1;
        if (row < mcnt) {
            float4*       dst = (float4*)(g_hbuf + (size_t)(m0 + row) * HID + nt * BN1 + (tid & 1) * 32);
            const float4* src = (const float4*)(Cs + row * CS1_STRIDE + (tid & 1) * 32);
#pragma unroll
            for (int i = 0; i < 8; i++) dst[i] = src[i];
        }
    }
}

// ---------------- phase-2: grouped GEMM (h @ w2) * gate ----------------------
#define BN2 128
#define BS2_STRIDE 136
#define BS2_TILE (BK * BS2_STRIDE)     /* 4352 floats */
#define FFN2_SMEM ((2 * AS_TILE + 2 * BS2_TILE) * 4)   /* 79872 B */
#define CS2_STRIDE 136

__global__ void __launch_bounds__(256, 2) ffn2_kernel() {
    extern __shared__ float smem[];
    float* As = smem;
    float* Bs = smem + 2 * AS_TILE;

    int e = blockIdx.z, nt = blockIdx.y, mt = blockIdx.x;
    int pbeg = g_offsets[e], pend = g_offsets[e + 1];
    int m0 = pbeg + mt * BM;
    if (m0 >= pend) return;
    int mcnt = pend - m0; if (mcnt > BM) mcnt = BM;

    int tid = threadIdx.x;
    int warp = tid >> 5, lane = tid & 31;
    int wm = warp & 3, wn = warp >> 2;

    int  arow   = tid >> 1;
    bool avalid = arow < mcnt;
    const float* asrc = g_hbuf + (size_t)(m0 + arow) * HID + (tid & 1) * 16;
    const float* w2p  = g_rw2 + (size_t)e * HID * EMB + (size_t)nt * BN2;

    float acc[2][8][4];
#pragma unroll
    for (int a = 0; a < 2; a++)
#pragma unroll
        for (int b = 0; b < 8; b++)
#pragma unroll
            for (int c = 0; c < 4; c++) acc[a][b][c] = 0.f;

    int r32 = tid >> 5, c32 = tid & 31;   // B-tile: 1024 f4, 4 passes

    // prologue
    {
#pragma unroll
        for (int i = 0; i < 4; i++)
            cp16(As + arow * AS_STRIDE + (tid & 1) * 16 + i * 4, asrc + i * 4, avalid);
#pragma unroll
        for (int j = 0; j < 4; j++) {
            int r = r32 + j * 8;
            cp16(Bs + r * BS2_STRIDE + c32 * 4, w2p + (size_t)r * EMB + c32 * 4, true);
        }
        CP_COMMIT;
    }

    const int NIT = HID / BK;
    for (int it = 0; it < NIT; ++it) {
        int cur = it & 1;
        if (it + 1 < NIT) {
            int k0 = (it + 1) * BK;
            int st = cur ^ 1;
            float* Ab = As + st * AS_TILE;
#pragma unroll
            for (int i = 0; i < 4; i++)
                cp16(Ab + arow * AS_STRIDE + (tid & 1) * 16 + i * 4, asrc + k0 + i * 4, avalid);
            float* Bb = Bs + st * BS2_TILE;
#pragma unroll
            for (int j = 0; j < 4; j++) {
                int r = r32 + j * 8;
                cp16(Bb + r * BS2_STRIDE + c32 * 4, w2p + (size_t)(k0 + r) * EMB + c32 * 4, true);
            }
        }
        CP_COMMIT;
        CP_WAIT1;
        __syncthreads();

        const float* Ab = As + cur * AS_TILE;
        const float* Bb = Bs + cur * BS2_TILE;
#pragma unroll
        for (int kk = 0; kk < BK; kk += 8) {
            uint32_t a[2][4];
            int ar  = wm * 32 + (lane >> 2);
            int acl = kk + (lane & 3);
#pragma unroll
            for (int mi = 0; mi < 2; mi++) {
                a[mi][0] = __float_as_uint(Ab[(ar + mi * 16)     * AS_STRIDE + acl]);
                a[mi][1] = __float_as_uint(Ab[(ar + mi * 16 + 8) * AS_STRIDE + acl]);
                a[mi][2] = __float_as_uint(Ab[(ar + mi * 16)     * AS_STRIDE + acl + 4]);
                a[mi][3] = __float_as_uint(Ab[(ar + mi * 16 + 8) * AS_STRIDE + acl + 4]);
            }
            int bk  = kk + (lane & 3);
            int bnb = wn * 64 + (lane >> 2);
#pragma unroll
            for (int ni = 0; ni < 8; ni++) {
                uint32_t b[2];
                b[0] = __float_as_uint(Bb[bk * BS2_STRIDE + bnb + ni * 8]);
                b[1] = __float_as_uint(Bb[(bk + 4) * BS2_STRIDE + bnb + ni * 8]);
#pragma unroll
                for (int mi = 0; mi < 2; mi++) mma_tf32(acc[mi][ni], a[mi], b);
            }
        }
        __syncthreads();
    }

    // epilogue: stage -> gate -> coalesced per-slot stores
    float* Cs = smem;
#pragma unroll
    for (int mi = 0; mi < 2; mi++)
#pragma unroll
        for (int ni = 0; ni < 8; ni++)
#pragma unroll
            for (int r = 0; r < 4; r++) {
                int row = wm * 32 + mi * 16 + (lane >> 2) + ((r >= 2) ? 8 : 0);
                int col = wn * 64 + ni * 8 + (lane & 3) * 2 + (r & 1);
                Cs[row * CS2_STRIDE + col] = acc[mi][ni][r];
            }
    __syncthreads();
    {
        int row = tid >> 1;
        if (row < mcnt) {
            int   p  = m0 + row;
            int   t  = g_pair_token[p];
            float gt = g_pair_gate[p];
            int   sl = g_pair_slot[p];
            float4*       dst = (float4*)(&g_contrib[sl][t][nt * BN2 + (tid & 1) * 64]);
            const float4* src = (const float4*)(Cs + row * CS2_STRIDE + (tid & 1) * 64);
#pragma unroll
            for (int i = 0; i < 16; i++) {
                float4 v = src[i];
                dst[i] = make_float4(v.x * gt, v.y * gt, v.z * gt, v.w * gt);
            }
        }
    }
}

// ---------------- final reduce ------------------------------------------------
__global__ void reduce_kernel(float* __restrict__ out) {
    size_t i = (size_t)blockIdx.x * blockDim.x + threadIdx.x;
    size_t n = (size_t)T_TOK * EMB / 4;
    if (i >= n) return;
    const float4* c0 = (const float4*)&g_contrib[0][0][0];
    const float4* c1 = (const float4*)&g_contrib[1][0][0];
    float4 a = c0[i], b = c1[i];
    ((float4*)out)[i] = make_float4(a.x + b.x, a.y + b.y, a.z + b.z, a.w + b.w);
}

// ---------------- launch ------------------------------------------------------
extern "C" void kernel_launch(void* const* d_in, const int* in_sizes, int n_in,
                              void* d_out, int out_size) {
    const float* x  = (const float*)d_in[0];
    const float* wr = (const float*)d_in[1];
    const float* w1 = (const float*)d_in[2];
    const float* w3 = (const float*)d_in[3];
    const float* w2 = (const float*)d_in[4];
    float* out = (float*)d_out;

    cudaFuncSetAttribute(ffn1_kernel, cudaFuncAttributeMaxDynamicSharedMemorySize, FFN1_SMEM);
    cudaFuncSetAttribute(ffn2_kernel, cudaFuncAttributeMaxDynamicSharedMemorySize, FFN2_SMEM);

    // launch order chosen so launch index 5 (ncu -s 5 -c 1) is ffn1_kernel
    preround_w_kernel<<<2368, 256>>>((const float4*)w1, (const float4*)w3, (const float4*)w2); // 0
    preround_x_kernel<<<1184, 256>>>((const float4*)x);                                        // 1
    router_kernel<<<(T_TOK * 32 + 255) / 256, 256>>>(x, wr);                                   // 2
    offsets_kernel<<<1, 32>>>();                                                               // 3
    scatter_kernel<<<(NPAIR + 255) / 256, 256>>>();                                            // 4

    dim3 g1(32, HID / BN1, NE);   // x = mt (innermost -> B-slice reuse in L2)
    ffn1_kernel<<<g1, 256, FFN1_SMEM>>>();                                                     // 5

    dim3 g2(32, EMB / BN2, NE);
    ffn2_kernel<<<g2, 256, FFN2_SMEM>>>();                                                     // 6

    reduce_kernel<<<((T_TOK * EMB / 4) + 255) / 256, 256>>>(out);                              // 7
}

// round 9
// speedup vs baseline: 1.0011x; 1.0011x over previous
#include <cuda_runtime.h>
#include <cstdint>
#include <math.h>

#define T_TOK 4096
#define EMB   1024
#define HID   2816
#define NE    8
#define NPAIR (T_TOK * 2)

// ---------------- device scratch ---------------------------------------------
__device__ int   g_counts[NE];
__device__ int   g_offsets[NE + 1];
__device__ int   g_cursor[NE];
__device__ int   g_tok_e[T_TOK][2];
__device__ float g_tok_p[T_TOK][2];
__device__ int   g_pair_token[NPAIR];
__device__ float g_pair_gate[NPAIR];
__device__ int   g_pair_slot[NPAIR];
__device__ float g_hbuf[(size_t)NPAIR * HID];        // 92 MB (tf32-rounded)
__device__ float g_contrib[2][T_TOK][EMB];           // 32 MB
__device__ float g_rx [(size_t)T_TOK * EMB];         // 16 MB  tf32-rounded x
__device__ float g_rw1[(size_t)NE * EMB * HID];      // 92 MB  tf32-rounded w1
__device__ float g_rw3[(size_t)NE * EMB * HID];      // 92 MB  tf32-rounded w3
__device__ float g_rw2[(size_t)NE * HID * EMB];      // 92 MB  tf32-rounded w2

// ---------------- helpers ----------------------------------------------------
__device__ __forceinline__ float to_tf32(float x) {
    uint32_t u;
    asm("cvt.rna.tf32.f32 %0, %1;" : "=r"(u) : "f"(x));
    return __uint_as_float(u);
}

__device__ __forceinline__ void mma_tf32(float c[4], const uint32_t a[4], const uint32_t b[2]) {
    asm volatile(
        "mma.sync.aligned.m16n8k8.row.col.f32.tf32.tf32.f32 "
        "{%0,%1,%2,%3}, {%4,%5,%6,%7}, {%8,%9}, {%0,%1,%2,%3};\n"
        : "+f"(c[0]), "+f"(c[1]), "+f"(c[2]), "+f"(c[3])
        : "r"(a[0]), "r"(a[1]), "r"(a[2]), "r"(a[3]),
          "r"(b[0]), "r"(b[1]));
}

__device__ __forceinline__ void cp16(float* sdst, const float* gsrc, bool p) {
    uint32_t s = (uint32_t)__cvta_generic_to_shared(sdst);
    asm volatile("cp.async.cg.shared.global [%0], [%1], 16, %2;\n"
                 :: "r"(s), "l"(gsrc), "r"(p ? 16 : 0));
}
#define CP_COMMIT asm volatile("cp.async.commit_group;\n" ::: "memory")
#define CP_WAIT1  asm volatile("cp.async.wait_group 1;\n" ::: "memory")

// ---------------- preround kernels -------------------------------------------
__global__ void preround_w_kernel(const float4* __restrict__ w1,
                                  const float4* __restrict__ w3,
                                  const float4* __restrict__ w2) {
    const int n4 = NE * EMB * HID / 4;
    float4* d1 = (float4*)g_rw1;
    float4* d3 = (float4*)g_rw3;
    float4* d2 = (float4*)g_rw2;
    int stride = gridDim.x * blockDim.x;
    for (int i = blockIdx.x * blockDim.x + threadIdx.x; i < n4; i += stride) {
        float4 a = w1[i], b = w3[i], c = w2[i];
        d1[i] = make_float4(to_tf32(a.x), to_tf32(a.y), to_tf32(a.z), to_tf32(a.w));
        d3[i] = make_float4(to_tf32(b.x), to_tf32(b.y), to_tf32(b.z), to_tf32(b.w));
        d2[i] = make_float4(to_tf32(c.x), to_tf32(c.y), to_tf32(c.z), to_tf32(c.w));
    }
}

__global__ void preround_x_kernel(const float4* __restrict__ x) {
    // also zero the routing metadata (fused so ffn1 is the 6th launch for ncu)
    if (blockIdx.x == 0 && threadIdx.x < NE) {
        g_counts[threadIdx.x] = 0; g_cursor[threadIdx.x] = 0;
    }
    const int n4 = T_TOK * EMB / 4;
    float4* dx = (float4*)g_rx;
    int stride = gridDim.x * blockDim.x;
    for (int i = blockIdx.x * blockDim.x + threadIdx.x; i < n4; i += stride) {
        float4 a = x[i];
        dx[i] = make_float4(to_tf32(a.x), to_tf32(a.y), to_tf32(a.z), to_tf32(a.w));
    }
}

// ---------------- router (one warp per token) --------------------------------
__global__ void router_kernel(const float* __restrict__ x, const float* __restrict__ wr) {
    int gw   = (blockIdx.x * blockDim.x + threadIdx.x) >> 5;
    int lane = threadIdx.x & 31;
    if (gw >= T_TOK) return;
    const float* xr = x + (size_t)gw * EMB;
    float acc[NE];
#pragma unroll
    for (int e = 0; e < NE; e++) acc[e] = 0.f;
    for (int k = lane; k < EMB; k += 32) {
        float  xv = xr[k];
        float4 wa = *(const float4*)(wr + k * NE);
        float4 wb = *(const float4*)(wr + k * NE + 4);
        acc[0] += xv * wa.x; acc[1] += xv * wa.y; acc[2] += xv * wa.z; acc[3] += xv * wa.w;
        acc[4] += xv * wb.x; acc[5] += xv * wb.y; acc[6] += xv * wb.z; acc[7] += xv * wb.w;
    }
#pragma unroll
    for (int e = 0; e < NE; e++)
#pragma unroll
        for (int o = 16; o > 0; o >>= 1) acc[e] += __shfl_xor_sync(0xffffffffu, acc[e], o);
    if (lane == 0) {
        int i0 = 0; float v0 = acc[0];
#pragma unroll
        for (int e = 1; e < NE; e++) if (acc[e] > v0) { v0 = acc[e]; i0 = e; }
        int i1 = -1; float v1 = -1e30f;
#pragma unroll
        for (int e = 0; e < NE; e++) if (e != i0 && acc[e] > v1) { v1 = acc[e]; i1 = e; }
        float p1 = 1.f / (1.f + expf(v0 - v1));
        float p0 = 1.f - p1;
        g_tok_e[gw][0] = i0; g_tok_e[gw][1] = i1;
        g_tok_p[gw][0] = p0; g_tok_p[gw][1] = p1;
        atomicAdd(&g_counts[i0], 1);
        atomicAdd(&g_counts[i1], 1);
    }
}

__global__ void offsets_kernel() {
    if (threadIdx.x == 0) {
        int s = 0;
        for (int e = 0; e < NE; e++) { g_offsets[e] = s; s += g_counts[e]; }
        g_offsets[NE] = s;
    }
}

__global__ void scatter_kernel() {
    int i = blockIdx.x * blockDim.x + threadIdx.x;
    if (i >= NPAIR) return;
    int t = i >> 1, k = i & 1;
    int e = g_tok_e[t][k];
    int pos = g_offsets[e] + atomicAdd(&g_cursor[e], 1);
    g_pair_token[pos] = t;
    g_pair_gate[pos]  = g_tok_p[t][k];
    g_pair_slot[pos]  = k;
}

// ---------------- phase-1: grouped GEMM + SwiGLU (cp.async 2-stage) ----------
#define BM  128
#define BN1 64
#define BK  32
#define AS_STRIDE  44          /* conflict-free, 16B aligned rows */
#define BS1_STRIDE 72
#define AS_TILE  (BM * AS_STRIDE)     /* 5632 floats */
#define BS1_TILE (BK * BS1_STRIDE)    /* 2304 floats */
#define FFN1_SMEM ((2 * AS_TILE + 4 * BS1_TILE) * 4)   /* 81920 B */
#define CS1_STRIDE 72

__global__ void __launch_bounds__(256, 2) ffn1_kernel() {
    extern __shared__ float smem[];
    float* As  = smem;                       // 2 stages
    float* B1s = smem + 2 * AS_TILE;         // 2 stages
    float* B3s = B1s + 2 * BS1_TILE;

    int e = blockIdx.z, nt = blockIdx.y, mt = blockIdx.x;
    int pbeg = g_offsets[e], pend = g_offsets[e + 1];
    int m0 = pbeg + mt * BM;
    if (m0 >= pend) return;
    int mcnt = pend - m0; if (mcnt > BM) mcnt = BM;

    int tid = threadIdx.x;
    int warp = tid >> 5, lane = tid & 31;
    int wm = warp & 3, wn = warp >> 2;

    int  arow   = tid >> 1;
    bool avalid = arow < mcnt;
    int  atok   = avalid ? g_pair_token[m0 + arow] : 0;
    const float* asrc = g_rx + (size_t)atok * EMB + (tid & 1) * 16;
    const float* w1p  = g_rw1 + (size_t)e * EMB * HID + (size_t)nt * BN1;
    const float* w3p  = g_rw3 + (size_t)e * EMB * HID + (size_t)nt * BN1;

    float ch[2][4][4], cg[2][4][4];
#pragma unroll
    for (int a = 0; a < 2; a++)
#pragma unroll
        for (int b = 0; b < 4; b++)
#pragma unroll
            for (int c = 0; c < 4; c++) { ch[a][b][c] = 0.f; cg[a][b][c] = 0.f; }

    int r16 = tid >> 4, c16 = tid & 15;    // B-tile mapping: 256 threads, 2 passes

    // prologue: stage 0
    {
        float* Ab = As;
#pragma unroll
        for (int i = 0; i < 4; i++)
            cp16(Ab + arow * AS_STRIDE + (tid & 1) * 16 + i * 4, asrc + i * 4, avalid);
#pragma unroll
        for (int j = 0; j < 2; j++) {
            int r = r16 + j * 16;
            cp16(B1s + r * BS1_STRIDE + c16 * 4, w1p + (size_t)r * HID + c16 * 4, true);
            cp16(B3s + r * BS1_STRIDE + c16 * 4, w3p + (size_t)r * HID + c16 * 4, true);
        }
        CP_COMMIT;
    }

    const int NIT = EMB / BK;
    for (int it = 0; it < NIT; ++it) {
        int cur = it & 1;
        if (it + 1 < NIT) {
            int k0 = (it + 1) * BK;
            int st = cur ^ 1;
            float* Ab = As + st * AS_TILE;
#pragma unroll
            for (int i = 0; i < 4; i++)
                cp16(Ab + arow * AS_STRIDE + (tid & 1) * 16 + i * 4, asrc + k0 + i * 4, avalid);
            float* B1b = B1s + st * BS1_TILE;
            float* B3b = B3s + st * BS1_TILE;
#pragma unroll
            for (int j = 0; j < 2; j++) {
                int r = r16 + j * 16;
                cp16(B1b + r * BS1_STRIDE + c16 * 4, w1p + (size_t)(k0 + r) * HID + c16 * 4, true);
                cp16(B3b + r * BS1_STRIDE + c16 * 4, w3p + (size_t)(k0 + r) * HID + c16 * 4, true);
            }
        }
        CP_COMMIT;
        CP_WAIT1;
        __syncthreads();

        const float* Ab  = As  + cur * AS_TILE;
        const float* B1b = B1s + cur * BS1_TILE;
        const float* B3b = B3s + cur * BS1_TILE;
#pragma unroll
        for (int kk = 0; kk < BK; kk += 8) {
            uint32_t a[2][4];
            int ar  = wm * 32 + (lane >> 2);
            int acl = kk + (lane & 3);
#pragma unroll
            for (int mi = 0; mi < 2; mi++) {
                a[mi][0] = __float_as_uint(Ab[(ar + mi * 16)     * AS_STRIDE + acl]);
                a[mi][1] = __float_as_uint(Ab[(ar + mi * 16 + 8) * AS_STRIDE + acl]);
                a[mi][2] = __float_as_uint(Ab[(ar + mi * 16)     * AS_STRIDE + acl + 4]);
                a[mi][3] = __float_as_uint(Ab[(ar + mi * 16 + 8) * AS_STRIDE + acl + 4]);
            }
            int bk  = kk + (lane & 3);
            int bnb = wn * 32 + (lane >> 2);
#pragma unroll
            for (int ni = 0; ni < 4; ni++) {
                uint32_t b1[2], b3[2];
                b1[0] = __float_as_uint(B1b[bk * BS1_STRIDE + bnb + ni * 8]);
                b1[1] = __float_as_uint(B1b[(bk + 4) * BS1_STRIDE + bnb + ni * 8]);
                b3[0] = __float_as_uint(B3b[bk * BS1_STRIDE + bnb + ni * 8]);
                b3[1] = __float_as_uint(B3b[(bk + 4) * BS1_STRIDE + bnb + ni * 8]);
#pragma unroll
                for (int mi = 0; mi < 2; mi++) {
                    mma_tf32(ch[mi][ni], a[mi], b1);
                    mma_tf32(cg[mi][ni], a[mi], b3);
                }
            }
        }
        __syncthreads();
    }

    // epilogue: silu(h)*g -> smem stage -> coalesced tf32-rounded stores
    float* Cs = smem;
#pragma unroll
    for (int mi = 0; mi < 2; mi++)
#pragma unroll
        for (int ni = 0; ni < 4; ni++)
#pragma unroll
            for (int r = 0; r < 4; r++) {
                int row = wm * 32 + mi * 16 + (lane >> 2) + ((r >= 2) ? 8 : 0);
                int col = wn * 32 + ni * 8 + (lane & 3) * 2 + (r & 1);
                float h = ch[mi][ni][r], g = cg[mi][ni][r];
                Cs[row * CS1_STRIDE + col] = to_tf32((h / (1.f + expf(-h))) * g);
            }
    __syncthreads();
    {
        int row = tid >> 1;
        if (row < mcnt) {
            float4*       dst = (float4*)(g_hbuf + (size_t)(m0 + row) * HID + nt * BN1 + (tid & 1) * 32);
            const float4* src = (const float4*)(Cs + row * CS1_STRIDE + (tid & 1) * 32);
#pragma unroll
            for (int i = 0; i < 8; i++) dst[i] = src[i];
        }
    }
}

// ---------------- phase-2: grouped GEMM (h @ w2) * gate ----------------------
#define BN2 128
#define BS2_STRIDE 136
#define BS2_TILE (BK * BS2_STRIDE)     /* 4352 floats */
#define FFN2_SMEM ((2 * AS_TILE + 2 * BS2_TILE) * 4)   /* 79872 B */
#define CS2_STRIDE 136

__global__ void __launch_bounds__(256, 2) ffn2_kernel() {
    extern __shared__ float smem[];
    float* As = smem;
    float* Bs = smem + 2 * AS_TILE;

    int e = blockIdx.z, nt = blockIdx.y, mt = blockIdx.x;
    int pbeg = g_offsets[e], pend = g_offsets[e + 1];
    int m0 = pbeg + mt * BM;
    if (m0 >= pend) return;
    int mcnt = pend - m0; if (mcnt > BM) mcnt = BM;

    int tid = threadIdx.x;
    int warp = tid >> 5, lane = tid & 31;
    int wm = warp & 3, wn = warp >> 2;

    int  arow   = tid >> 1;
    bool avalid = arow < mcnt;
    const float* asrc = g_hbuf + (size_t)(m0 + arow) * HID + (tid & 1) * 16;
    const float* w2p  = g_rw2 + (size_t)e * HID * EMB + (size_t)nt * BN2;

    float acc[2][8][4];
#pragma unroll
    for (int a = 0; a < 2; a++)
#pragma unroll
        for (int b = 0; b < 8; b++)
#pragma unroll
            for (int c = 0; c < 4; c++) acc[a][b][c] = 0.f;

    int r32 = tid >> 5, c32 = tid & 31;   // B-tile: 1024 f4, 4 passes

    // prologue
    {
#pragma unroll
        for (int i = 0; i < 4; i++)
            cp16(As + arow * AS_STRIDE + (tid & 1) * 16 + i * 4, asrc + i * 4, avalid);
#pragma unroll
        for (int j = 0; j < 4; j++) {
            int r = r32 + j * 8;
            cp16(Bs + r * BS2_STRIDE + c32 * 4, w2p + (size_t)r * EMB + c32 * 4, true);
        }
        CP_COMMIT;
    }

    const int NIT = HID / BK;
    for (int it = 0; it < NIT; ++it) {
        int cur = it & 1;
        if (it + 1 < NIT) {
            int k0 = (it + 1) * BK;
            int st = cur ^ 1;
            float* Ab = As + st * AS_TILE;
#pragma unroll
            for (int i = 0; i < 4; i++)
                cp16(Ab + arow * AS_STRIDE + (tid & 1) * 16 + i * 4, asrc + k0 + i * 4, avalid);
            float* Bb = Bs + st * BS2_TILE;
#pragma unroll
            for (int j = 0; j < 4; j++) {
                int r = r32 + j * 8;
                cp16(Bb + r * BS2_STRIDE + c32 * 4, w2p + (size_t)(k0 + r) * EMB + c32 * 4, true);
            }
        }
        CP_COMMIT;
        CP_WAIT1;
        __syncthreads();

        const float* Ab = As + cur * AS_TILE;
        const float* Bb = Bs + cur * BS2_TILE;
#pragma unroll
        for (int kk = 0; kk < BK; kk += 8) {
            uint32_t a[2][4];
            int ar  = wm * 32 + (lane >> 2);
            int acl = kk + (lane & 3);
#pragma unroll
            for (int mi = 0; mi < 2; mi++) {
                a[mi][0] = __float_as_uint(Ab[(ar + mi * 16)     * AS_STRIDE + acl]);
                a[mi][1] = __float_as_uint(Ab[(ar + mi * 16 + 8) * AS_STRIDE + acl]);
                a[mi][2] = __float_as_uint(Ab[(ar + mi * 16)     * AS_STRIDE + acl + 4]);
                a[mi][3] = __float_as_uint(Ab[(ar + mi * 16 + 8) * AS_STRIDE + acl + 4]);
            }
            int bk  = kk + (lane & 3);
            int bnb = wn * 64 + (lane >> 2);
#pragma unroll
            for (int ni = 0; ni < 8; ni++) {
                uint32_t b[2];
                b[0] = __float_as_uint(Bb[bk * BS2_STRIDE + bnb + ni * 8]);
                b[1] = __float_as_uint(Bb[(bk + 4) * BS2_STRIDE + bnb + ni * 8]);
#pragma unroll
                for (int mi = 0; mi < 2; mi++) mma_tf32(acc[mi][ni], a[mi], b);
            }
        }
        __syncthreads();
    }

    // epilogue: stage -> gate -> coalesced per-slot stores
    float* Cs = smem;
#pragma unroll
    for (int mi = 0; mi < 2; mi++)
#pragma unroll
        for (int ni = 0; ni < 8; ni++)
#pragma unroll
            for (int r = 0; r < 4; r++) {
                int row = wm * 32 + mi * 16 + (lane >> 2) + ((r >= 2) ? 8 : 0);
                int col = wn * 64 + ni * 8 + (lane & 3) * 2 + (r & 1);
                Cs[row * CS2_STRIDE + col] = acc[mi][ni][r];
            }
    __syncthreads();
    {
        int row = tid >> 1;
        if (row < mcnt) {
            int   p  = m0 + row;
            int   t  = g_pair_token[p];
            float gt = g_pair_gate[p];
            int   sl = g_pair_slot[p];
            float4*       dst = (float4*)(&g_contrib[sl][t][nt * BN2 + (tid & 1) * 64]);
            const float4* src = (const float4*)(Cs + row * CS2_STRIDE + (tid & 1) * 64);
#pragma unroll
            for (int i = 0; i < 16; i++) {
                float4 v = src[i];
                dst[i] = make_float4(v.x * gt, v.y * gt, v.z * gt, v.w * gt);
            }
        }
    }
}

// ---------------- final reduce ------------------------------------------------
__global__ void reduce_kernel(float* __restrict__ out) {
    size_t i = (size_t)blockIdx.x * blockDim.x + threadIdx.x;
    size_t n = (size_t)T_TOK * EMB / 4;
    if (i >= n) return;
    const float4* c0 = (const float4*)&g_contrib[0][0][0];
    const float4* c1 = (const float4*)&g_contrib[1][0][0];
    float4 a = c0[i], b = c1[i];
    ((float4*)out)[i] = make_float4(a.x + b.x, a.y + b.y, a.z + b.z, a.w + b.w);
}

// ---------------- launch ------------------------------------------------------
extern "C" void kernel_launch(void* const* d_in, const int* in_sizes, int n_in,
                              void* d_out, int out_size) {
    const float* x  = (const float*)d_in[0];
    const float* wr = (const float*)d_in[1];
    const float* w1 = (const float*)d_in[2];
    const float* w3 = (const float*)d_in[3];
    const float* w2 = (const float*)d_in[4];
    float* out = (float*)d_out;

    cudaFuncSetAttribute(ffn1_kernel, cudaFuncAttributeMaxDynamicSharedMemorySize, FFN1_SMEM);
    cudaFuncSetAttribute(ffn2_kernel, cudaFuncAttributeMaxDynamicSharedMemorySize, FFN2_SMEM);

    // launch order chosen so launch index 5 (ncu -s 5 -c 1) is ffn1_kernel
    preround_w_kernel<<<2368, 256>>>((const float4*)w1, (const float4*)w3, (const float4*)w2); // 0
    preround_x_kernel<<<1184, 256>>>((const float4*)x);                                        // 1
    router_kernel<<<(T_TOK * 32 + 255) / 256, 256>>>(x, wr);                                   // 2
    offsets_kernel<<<1, 32>>>();                                                               // 3
    scatter_kernel<<<(NPAIR + 255) / 256, 256>>>();                                            // 4

    dim3 g1(32, HID / BN1, NE);   // x = mt (innermost -> B-slice reuse in L2)
    ffn1_kernel<<<g1, 256, FFN1_SMEM>>>();                                                     // 5

    dim3 g2(32, EMB / BN2, NE);
    ffn2_kernel<<<g2, 256, FFN2_SMEM>>>();                                                     // 6

    reduce_kernel<<<((T_TOK * EMB / 4) + 255) / 256, 256>>>(out);                              // 7
}

// round 11
// speedup vs baseline: 1.6909x; 1.6890x over previous
#include <cuda_runtime.h>
#include <cuda_fp16.h>
#include <cstdint>
#include <math.h>

#define T_TOK 4096
#define EMB   1024
#define HID   2816
#define NE    8
#define NPAIR (T_TOK * 2)

// ---------------- device scratch ---------------------------------------------
__device__ int    g_offsets[NE + 1];
__device__ int    g_tok_e[T_TOK][2];
__device__ float  g_tok_p[T_TOK][2];
__device__ int    g_pair_token[NPAIR];
__device__ float  g_pair_gate[NPAIR];
__device__ int    g_pair_slot[NPAIR];
__device__ __align__(16) __half g_rx [(size_t)T_TOK * EMB];     // fp16 x
__device__ __align__(16) __half g_w1t[(size_t)NE * HID * EMB];  // w1^T [e][n][k]
__device__ __align__(16) __half g_w3t[(size_t)NE * HID * EMB];  // w3^T
__device__ __align__(16) __half g_w2t[(size_t)NE * EMB * HID];  // w2^T [e][n][k]
__device__ __align__(16) __half g_hbuf[(size_t)NPAIR * HID];    // silu(h)*g fp16
__device__ float  g_contrib[2][T_TOK][EMB];

// ---------------- helpers ----------------------------------------------------
__device__ __forceinline__ void mma_f16(float c[4], const uint32_t a[4], uint32_t b0, uint32_t b1) {
    asm volatile(
        "mma.sync.aligned.m16n8k16.row.col.f32.f16.f16.f32 "
        "{%0,%1,%2,%3}, {%4,%5,%6,%7}, {%8,%9}, {%0,%1,%2,%3};\n"
        : "+f"(c[0]), "+f"(c[1]), "+f"(c[2]), "+f"(c[3])
        : "r"(a[0]), "r"(a[1]), "r"(a[2]), "r"(a[3]), "r"(b0), "r"(b1));
}

__device__ __forceinline__ void cp16(const __half* sdst, const __half* gsrc, uint32_t pbytes) {
    uint32_t s = (uint32_t)__cvta_generic_to_shared(sdst);
    asm volatile("cp.async.cg.shared.global [%0], [%1], 16, %2;\n"
                 :: "r"(s), "l"(gsrc), "r"(pbytes));
}
#define CP_COMMIT asm volatile("cp.async.commit_group;\n" ::: "memory")
#define CP_WAIT1  asm volatile("cp.async.wait_group 1;\n" ::: "memory")

// ---------------- kernel 0: router + x->fp16 ---------------------------------
__global__ void router_kernel(const float* __restrict__ x, const float* __restrict__ wr) {
    int gw   = (blockIdx.x * blockDim.x + threadIdx.x) >> 5;
    int lane = threadIdx.x & 31;
    if (gw >= T_TOK) return;
    const float* xr = x + (size_t)gw * EMB;
    __half*      ox = g_rx + (size_t)gw * EMB;
    float acc[NE];
#pragma unroll
    for (int e = 0; e < NE; e++) acc[e] = 0.f;
    for (int k = lane; k < EMB; k += 32) {
        float xv = xr[k];
        ox[k] = __float2half_rn(xv);
        float4 wa = *(const float4*)(wr + k * NE);
        float4 wb = *(const float4*)(wr + k * NE + 4);
        acc[0] += xv * wa.x; acc[1] += xv * wa.y; acc[2] += xv * wa.z; acc[3] += xv * wa.w;
        acc[4] += xv * wb.x; acc[5] += xv * wb.y; acc[6] += xv * wb.z; acc[7] += xv * wb.w;
    }
#pragma unroll
    for (int e = 0; e < NE; e++)
#pragma unroll
        for (int o = 16; o > 0; o >>= 1) acc[e] += __shfl_xor_sync(0xffffffffu, acc[e], o);
    if (lane == 0) {
        int i0 = 0; float v0 = acc[0];
#pragma unroll
        for (int e = 1; e < NE; e++) if (acc[e] > v0) { v0 = acc[e]; i0 = e; }
        int i1 = -1; float v1 = -1e30f;
#pragma unroll
        for (int e = 0; e < NE; e++) if (e != i0 && acc[e] > v1) { v1 = acc[e]; i1 = e; }
        float p1 = 1.f / (1.f + expf(v0 - v1));
        g_tok_e[gw][0] = i0; g_tok_e[gw][1] = i1;
        g_tok_p[gw][0] = 1.f - p1; g_tok_p[gw][1] = p1;
    }
}

// ---------------- kernel 1: offsets + scatter (single CTA) --------------------
__global__ void offsets_scatter_kernel() {
    __shared__ int hist[8][NE];
    __shared__ int soff[NE];
    __shared__ int scur[NE];
    int tid = threadIdx.x, wid = tid >> 5;
    if (tid < 64) ((int*)hist)[tid] = 0;
    __syncthreads();
    for (int i = tid; i < NPAIR; i += 256) {
        int t = i >> 1, k = i & 1;
        atomicAdd(&hist[wid][g_tok_e[t][k]], 1);
    }
    __syncthreads();
    if (tid == 0) {
        int s = 0;
        for (int e = 0; e < NE; e++) {
            int c = 0;
            for (int w = 0; w < 8; w++) c += hist[w][e];
            g_offsets[e] = s; soff[e] = s; s += c;
        }
        g_offsets[NE] = s;
    }
    if (tid < NE) scur[tid] = 0;
    __syncthreads();
    for (int i = tid; i < NPAIR; i += 256) {
        int t = i >> 1, k = i & 1;
        int e = g_tok_e[t][k];
        int pos = soff[e] + atomicAdd(&scur[e], 1);
        g_pair_token[pos] = t;
        g_pair_gate[pos]  = g_tok_p[t][k];
        g_pair_slot[pos]  = k;
    }
}

// ---------------- kernel 2: weights -> fp16, transposed to [e][n][k] ---------
// grid (88, 32, 24): z 0-7 w1[e], 8-15 w3[e], 16-23 w2[e].  256 threads.
__global__ void preround_w_kernel(const float* __restrict__ w1,
                                  const float* __restrict__ w3,
                                  const float* __restrict__ w2) {
    __shared__ float tile[32][33];
    int z = blockIdx.z;
    int r = threadIdx.x >> 5, c = threadIdx.x & 31;
    if (z < 16) {
        int e = z & 7;
        const float* src = (z >= 8 ? w3 : w1) + (size_t)e * EMB * HID;
        __half*      dst = (z >= 8 ? g_w3t : g_w1t) + (size_t)e * HID * EMB;
        int n0 = blockIdx.x * 32;   // HID
        int k0 = blockIdx.y * 32;   // EMB
#pragma unroll
        for (int i = 0; i < 4; i++)
            tile[r + i * 8][c] = src[(size_t)(k0 + r + i * 8) * HID + n0 + c];
        __syncthreads();
#pragma unroll
        for (int i = 0; i < 4; i++)
            dst[(size_t)(n0 + r + i * 8) * EMB + k0 + c] = __float2half_rn(tile[c][r + i * 8]);
    } else {
        int e = z - 16;
        const float* src = w2 + (size_t)e * HID * EMB;
        __half*      dst = g_w2t + (size_t)e * EMB * HID;
        int k0 = blockIdx.x * 32;   // HID
        int n0 = blockIdx.y * 32;   // EMB
#pragma unroll
        for (int i = 0; i < 4; i++)
            tile[r + i * 8][c] = src[(size_t)(k0 + r + i * 8) * EMB + n0 + c];
        __syncthreads();
#pragma unroll
        for (int i = 0; i < 4; i++)
            dst[(size_t)(n0 + r + i * 8) * HID + k0 + c] = __float2half_rn(tile[c][r + i * 8]);
    }
}

// ---------------- kernel 3: ffn1 fp16 GEMM + SwiGLU --------------------------
// CTA: 128 pairs x 64 hid cols, both w1 & w3. K = EMB, BK = 32 halves.
#define BK 32
#define ASTR 40   /* half stride: 80B rows -> 16B aligned + conflict-free */

__global__ void __launch_bounds__(256) ffn1_kernel() {
    __shared__ __half As [2][128][ASTR];
    __shared__ __half B1s[2][64][ASTR];
    __shared__ __half B3s[2][64][ASTR];

    int e = blockIdx.z, nt = blockIdx.y, mt = blockIdx.x;
    int pbeg = g_offsets[e], pend = g_offsets[e + 1];
    int m0 = pbeg + mt * 128;
    if (m0 >= pend) return;
    int mcnt = pend - m0; if (mcnt > 128) mcnt = 128;

    int tid = threadIdx.x;
    int warp = tid >> 5, lane = tid & 31;
    int wm = warp & 3, wn = warp >> 2;     // 4x2 warps, warp tile 32x32
    int gid = lane >> 2, tig = lane & 3;

    int  arow = tid >> 1, aseg = tid & 1;
    bool av   = arow < mcnt;
    int  atok = av ? g_pair_token[m0 + arow] : 0;
    const __half* asrc = g_rx + (size_t)atok * EMB + aseg * 16;
    uint32_t apb = av ? 16u : 0u;

    int brow = tid >> 2, bseg = tid & 3;
    const __half* b1b = g_w1t + ((size_t)e * HID + (size_t)nt * 64 + brow) * EMB + bseg * 8;
    const __half* b3b = g_w3t + ((size_t)e * HID + (size_t)nt * 64 + brow) * EMB + bseg * 8;

    float ch[2][4][4], cg[2][4][4];
#pragma unroll
    for (int a = 0; a < 2; a++)
#pragma unroll
        for (int b = 0; b < 4; b++)
#pragma unroll
            for (int c = 0; c < 4; c++) { ch[a][b][c] = 0.f; cg[a][b][c] = 0.f; }

    // prologue
    {
        cp16(&As[0][arow][aseg * 16],     asrc,     apb);
        cp16(&As[0][arow][aseg * 16 + 8], asrc + 8, apb);
        cp16(&B1s[0][brow][bseg * 8], b1b, 16);
        cp16(&B3s[0][brow][bseg * 8], b3b, 16);
        CP_COMMIT;
    }

    const int NIT = EMB / BK;
    for (int it = 0; it < NIT; ++it) {
        int cur = it & 1;
        if (it + 1 < NIT) {
            int k0 = (it + 1) * BK;
            int st = cur ^ 1;
            cp16(&As[st][arow][aseg * 16],     asrc + k0,     apb);
            cp16(&As[st][arow][aseg * 16 + 8], asrc + k0 + 8, apb);
            cp16(&B1s[st][brow][bseg * 8], b1b + k0, 16);
            cp16(&B3s[st][brow][bseg * 8], b3b + k0, 16);
        }
        CP_COMMIT;
        CP_WAIT1;
        __syncthreads();

#pragma unroll
        for (int kk = 0; kk < BK; kk += 16) {
            uint32_t a[2][4];
#pragma unroll
            for (int mi = 0; mi < 2; mi++) {
                int r0 = wm * 32 + mi * 16 + gid;
                a[mi][0] = *(const uint32_t*)&As[cur][r0][kk + tig * 2];
                a[mi][1] = *(const uint32_t*)&As[cur][r0 + 8][kk + tig * 2];
                a[mi][2] = *(const uint32_t*)&As[cur][r0][kk + 8 + tig * 2];
                a[mi][3] = *(const uint32_t*)&As[cur][r0 + 8][kk + 8 + tig * 2];
            }
#pragma unroll
            for (int ni = 0; ni < 4; ni++) {
                int n = wn * 32 + ni * 8 + gid;
                uint32_t b10 = *(const uint32_t*)&B1s[cur][n][kk + tig * 2];
                uint32_t b11 = *(const uint32_t*)&B1s[cur][n][kk + 8 + tig * 2];
                uint32_t b30 = *(const uint32_t*)&B3s[cur][n][kk + tig * 2];
                uint32_t b31 = *(const uint32_t*)&B3s[cur][n][kk + 8 + tig * 2];
#pragma unroll
                for (int mi = 0; mi < 2; mi++) {
                    mma_f16(ch[mi][ni], a[mi], b10, b11);
                    mma_f16(cg[mi][ni], a[mi], b30, b31);
                }
            }
        }
        __syncthreads();
    }

    // epilogue: silu(h)*g -> fp16 hbuf (half2 stores)
#pragma unroll
    for (int mi = 0; mi < 2; mi++) {
        int r0 = wm * 32 + mi * 16 + gid;
#pragma unroll
        for (int ni = 0; ni < 4; ni++) {
            int colg = nt * 64 + wn * 32 + ni * 8 + tig * 2;
            if (r0 < mcnt) {
                float h0 = ch[mi][ni][0], g0 = cg[mi][ni][0];
                float h1 = ch[mi][ni][1], g1 = cg[mi][ni][1];
                __half2 v = __floats2half2_rn((h0 / (1.f + expf(-h0))) * g0,
                                              (h1 / (1.f + expf(-h1))) * g1);
                *(__half2*)&g_hbuf[(size_t)(m0 + r0) * HID + colg] = v;
            }
            if (r0 + 8 < mcnt) {
                float h0 = ch[mi][ni][2], g0 = cg[mi][ni][2];
                float h1 = ch[mi][ni][3], g1 = cg[mi][ni][3];
                __half2 v = __floats2half2_rn((h0 / (1.f + expf(-h0))) * g0,
                                              (h1 / (1.f + expf(-h1))) * g1);
                *(__half2*)&g_hbuf[(size_t)(m0 + r0 + 8) * HID + colg] = v;
            }
        }
    }
}

// ---------------- kernel 4: ffn2 fp16 GEMM (h @ w2) * gate -------------------
__global__ void __launch_bounds__(256) ffn2_kernel() {
    __shared__ __half As[2][128][ASTR];
    __shared__ __half Bs[2][128][ASTR];

    int e = blockIdx.z, nt = blockIdx.y, mt = blockIdx.x;
    int pbeg = g_offsets[e], pend = g_offsets[e + 1];
    int m0 = pbeg + mt * 128;
    if (m0 >= pend) return;
    int mcnt = pend - m0; if (mcnt > 128) mcnt = 128;

    int tid = threadIdx.x;
    int warp = tid >> 5, lane = tid & 31;
    int wm = warp & 3, wn = warp >> 2;     // warp tile 32 rows x 64 cols
    int gid = lane >> 2, tig = lane & 3;

    int  arow = tid >> 1, aseg = tid & 1;
    bool av   = arow < mcnt;
    const __half* asrc = g_hbuf + (size_t)(m0 + (av ? arow : 0)) * HID + aseg * 16;
    uint32_t apb = av ? 16u : 0u;

    const __half* b2b = g_w2t + ((size_t)e * EMB + (size_t)nt * 128 + arow) * HID + aseg * 16;

    float acc[2][8][4];
#pragma unroll
    for (int a = 0; a < 2; a++)
#pragma unroll
        for (int b = 0; b < 8; b++)
#pragma unroll
            for (int c = 0; c < 4; c++) acc[a][b][c] = 0.f;

    // prologue
    {
        cp16(&As[0][arow][aseg * 16],     asrc,     apb);
        cp16(&As[0][arow][aseg * 16 + 8], asrc + 8, apb);
        cp16(&Bs[0][arow][aseg * 16],     b2b,     16);
        cp16(&Bs[0][arow][aseg * 16 + 8], b2b + 8, 16);
        CP_COMMIT;
    }

    const int NIT = HID / BK;
    for (int it = 0; it < NIT; ++it) {
        int cur = it & 1;
        if (it + 1 < NIT) {
            int k0 = (it + 1) * BK;
            int st = cur ^ 1;
            cp16(&As[st][arow][aseg * 16],     asrc + k0,     apb);
            cp16(&As[st][arow][aseg * 16 + 8], asrc + k0 + 8, apb);
            cp16(&Bs[st][arow][aseg * 16],     b2b + k0,     16);
            cp16(&Bs[st][arow][aseg * 16 + 8], b2b + k0 + 8, 16);
        }
        CP_COMMIT;
        CP_WAIT1;
        __syncthreads();

#pragma unroll
        for (int kk = 0; kk < BK; kk += 16) {
            uint32_t a[2][4];
#pragma unroll
            for (int mi = 0; mi < 2; mi++) {
                int r0 = wm * 32 + mi * 16 + gid;
                a[mi][0] = *(const uint32_t*)&As[cur][r0][kk + tig * 2];
                a[mi][1] = *(const uint32_t*)&As[cur][r0 + 8][kk + tig * 2];
                a[mi][2] = *(const uint32_t*)&As[cur][r0][kk + 8 + tig * 2];
                a[mi][3] = *(const uint32_t*)&As[cur][r0 + 8][kk + 8 + tig * 2];
            }
#pragma unroll
            for (int ni = 0; ni < 8; ni++) {
                int n = wn * 64 + ni * 8 + gid;
                uint32_t b0 = *(const uint32_t*)&Bs[cur][n][kk + tig * 2];
                uint32_t b1 = *(const uint32_t*)&Bs[cur][n][kk + 8 + tig * 2];
#pragma unroll
                for (int mi = 0; mi < 2; mi++) mma_f16(acc[mi][ni], a[mi], b0, b1);
            }
        }
        __syncthreads();
    }

    // epilogue: gate * acc -> per-slot contribution buffer (float2 stores)
#pragma unroll
    for (int mi = 0; mi < 2; mi++) {
        int r0 = wm * 32 + mi * 16 + gid;
        int   t0 = 0, t1 = 0, s0 = 0, s1 = 0;
        float gt0 = 0.f, gt1 = 0.f;
        bool v0 = r0 < mcnt, v1 = (r0 + 8) < mcnt;
        if (v0) { int p = m0 + r0;     t0 = g_pair_token[p]; gt0 = g_pair_gate[p]; s0 = g_pair_slot[p]; }
        if (v1) { int p = m0 + r0 + 8; t1 = g_pair_token[p]; gt1 = g_pair_gate[p]; s1 = g_pair_slot[p]; }
#pragma unroll
        for (int ni = 0; ni < 8; ni++) {
            int colg = nt * 128 + wn * 64 + ni * 8 + tig * 2;
            if (v0) {
                float2 v = make_float2(acc[mi][ni][0] * gt0, acc[mi][ni][1] * gt0);
                *(float2*)&g_contrib[s0][t0][colg] = v;
            }
            if (v1) {
                float2 v = make_float2(acc[mi][ni][2] * gt1, acc[mi][ni][3] * gt1);
                *(float2*)&g_contrib[s1][t1][colg] = v;
            }
        }
    }
}

// ---------------- kernel 5: final reduce -------------------------------------
__global__ void reduce_kernel(float* __restrict__ out) {
    size_t i = (size_t)blockIdx.x * blockDim.x + threadIdx.x;
    size_t n = (size_t)T_TOK * EMB / 4;
    if (i >= n) return;
    const float4* c0 = (const float4*)&g_contrib[0][0][0];
    const float4* c1 = (const float4*)&g_contrib[1][0][0];
    float4 a = c0[i], b = c1[i];
    ((float4*)out)[i] = make_float4(a.x + b.x, a.y + b.y, a.z + b.z, a.w + b.w);
}

// ---------------- launch ------------------------------------------------------
extern "C" void kernel_launch(void* const* d_in, const int* in_sizes, int n_in,
                              void* d_out, int out_size) {
    const float* x  = (const float*)d_in[0];
    const float* wr = (const float*)d_in[1];
    const float* w1 = (const float*)d_in[2];
    const float* w3 = (const float*)d_in[3];
    const float* w2 = (const float*)d_in[4];
    float* out = (float*)d_out;

    router_kernel<<<(T_TOK * 32 + 255) / 256, 256>>>(x, wr);           // 0
    offsets_scatter_kernel<<<1, 256>>>();                              // 1
    preround_w_kernel<<<dim3(88, 32, 24), 256>>>(w1, w3, w2);          // 2

    ffn1_kernel<<<dim3(32, HID / 64, NE), 256>>>();                    // 3  <- ncu capture
    ffn2_kernel<<<dim3(32, EMB / 128, NE), 256>>>();                   // 4
    reduce_kernel<<<((T_TOK * EMB / 4) + 255) / 256, 256>>>(out);      // 5
}

// round 12
// speedup vs baseline: 1.8448x; 1.0910x over previous
#include <cuda_runtime.h>
#include <cuda_fp16.h>
#include <cstdint>
#include <math.h>

#define T_TOK 4096
#define EMB   1024
#define HID   2816
#define NE    8
#define NPAIR (T_TOK * 2)

// ---------------- device scratch ---------------------------------------------
__device__ int    g_offsets[NE + 1];
__device__ int    g_tok_e[T_TOK][2];
__device__ float  g_tok_p[T_TOK][2];
__device__ int    g_pair_token[NPAIR];
__device__ float  g_pair_gate[NPAIR];
__device__ int    g_pair_slot[NPAIR];
__device__ __align__(16) __half g_rx [(size_t)T_TOK * EMB];     // fp16 x
__device__ __align__(16) __half g_w1t[(size_t)NE * HID * EMB];  // w1^T [e][n][k]
__device__ __align__(16) __half g_w3t[(size_t)NE * HID * EMB];  // w3^T
__device__ __align__(16) __half g_w2t[(size_t)NE * EMB * HID];  // w2^T [e][n][k]
__device__ __align__(16) __half g_hbuf[(size_t)NPAIR * HID];    // silu(h)*g fp16
__device__ float  g_contrib[2][T_TOK][EMB];

// ---------------- helpers ----------------------------------------------------
__device__ __forceinline__ void mma_f16(float c[4], const uint32_t a[4], uint32_t b0, uint32_t b1) {
    asm volatile(
        "mma.sync.aligned.m16n8k16.row.col.f32.f16.f16.f32 "
        "{%0,%1,%2,%3}, {%4,%5,%6,%7}, {%8,%9}, {%0,%1,%2,%3};\n"
        : "+f"(c[0]), "+f"(c[1]), "+f"(c[2]), "+f"(c[3])
        : "r"(a[0]), "r"(a[1]), "r"(a[2]), "r"(a[3]), "r"(b0), "r"(b1));
}

__device__ __forceinline__ void ldsm4(uint32_t& r0, uint32_t& r1, uint32_t& r2, uint32_t& r3,
                                      uint32_t addr) {
    asm volatile("ldmatrix.sync.aligned.m8n8.x4.shared.b16 {%0,%1,%2,%3}, [%4];"
                 : "=r"(r0), "=r"(r1), "=r"(r2), "=r"(r3) : "r"(addr));
}

__device__ __forceinline__ void cpa(void* sdst, const void* gsrc, uint32_t pbytes) {
    uint32_t s = (uint32_t)__cvta_generic_to_shared(sdst);
    asm volatile("cp.async.cg.shared.global [%0], [%1], 16, %2;\n"
                 :: "r"(s), "l"(gsrc), "r"(pbytes));
}
#define CP_COMMIT asm volatile("cp.async.commit_group;\n" ::: "memory")
#define CP_WAIT1  asm volatile("cp.async.wait_group 1;\n" ::: "memory")
#define CP_WAIT0  asm volatile("cp.async.wait_group 0;\n" ::: "memory")

// ---------------- kernel 0: router + x->fp16 ---------------------------------
__global__ void router_kernel(const float* __restrict__ x, const float* __restrict__ wr) {
    int gw   = (blockIdx.x * blockDim.x + threadIdx.x) >> 5;
    int lane = threadIdx.x & 31;
    if (gw >= T_TOK) return;
    const float* xr = x + (size_t)gw * EMB;
    __half*      ox = g_rx + (size_t)gw * EMB;
    float acc[NE];
#pragma unroll
    for (int e = 0; e < NE; e++) acc[e] = 0.f;
    for (int k = lane; k < EMB; k += 32) {
        float xv = xr[k];
        ox[k] = __float2half_rn(xv);
        float4 wa = *(const float4*)(wr + k * NE);
        float4 wb = *(const float4*)(wr + k * NE + 4);
        acc[0] += xv * wa.x; acc[1] += xv * wa.y; acc[2] += xv * wa.z; acc[3] += xv * wa.w;
        acc[4] += xv * wb.x; acc[5] += xv * wb.y; acc[6] += xv * wb.z; acc[7] += xv * wb.w;
    }
#pragma unroll
    for (int e = 0; e < NE; e++)
#pragma unroll
        for (int o = 16; o > 0; o >>= 1) acc[e] += __shfl_xor_sync(0xffffffffu, acc[e], o);
    if (lane == 0) {
        int i0 = 0; float v0 = acc[0];
#pragma unroll
        for (int e = 1; e < NE; e++) if (acc[e] > v0) { v0 = acc[e]; i0 = e; }
        int i1 = -1; float v1 = -1e30f;
#pragma unroll
        for (int e = 0; e < NE; e++) if (e != i0 && acc[e] > v1) { v1 = acc[e]; i1 = e; }
        float p1 = 1.f / (1.f + expf(v0 - v1));
        g_tok_e[gw][0] = i0; g_tok_e[gw][1] = i1;
        g_tok_p[gw][0] = 1.f - p1; g_tok_p[gw][1] = p1;
    }
}

// ---------------- kernel 1: offsets + scatter (single CTA) --------------------
__global__ void offsets_scatter_kernel() {
    __shared__ int hist[8][NE];
    __shared__ int soff[NE];
    __shared__ int scur[NE];
    int tid = threadIdx.x, wid = tid >> 5;
    if (tid < 64) ((int*)hist)[tid] = 0;
    __syncthreads();
    for (int i = tid; i < NPAIR; i += 256) {
        int t = i >> 1, k = i & 1;
        atomicAdd(&hist[wid][g_tok_e[t][k]], 1);
    }
    __syncthreads();
    if (tid == 0) {
        int s = 0;
        for (int e = 0; e < NE; e++) {
            int c = 0;
            for (int w = 0; w < 8; w++) c += hist[w][e];
            g_offsets[e] = s; soff[e] = s; s += c;
        }
        g_offsets[NE] = s;
    }
    if (tid < NE) scur[tid] = 0;
    __syncthreads();
    for (int i = tid; i < NPAIR; i += 256) {
        int t = i >> 1, k = i & 1;
        int e = g_tok_e[t][k];
        int pos = soff[e] + atomicAdd(&scur[e], 1);
        g_pair_token[pos] = t;
        g_pair_gate[pos]  = g_tok_p[t][k];
        g_pair_slot[pos]  = k;
    }
}

// ---------------- kernel 2: weights -> fp16, transposed to [e][n][k] ---------
__global__ void preround_w_kernel(const float* __restrict__ w1,
                                  const float* __restrict__ w3,
                                  const float* __restrict__ w2) {
    __shared__ float tile[32][33];
    int z = blockIdx.z;
    int r = threadIdx.x >> 5, c = threadIdx.x & 31;
    if (z < 16) {
        int e = z & 7;
        const float* src = (z >= 8 ? w3 : w1) + (size_t)e * EMB * HID;
        __half*      dst = (z >= 8 ? g_w3t : g_w1t) + (size_t)e * HID * EMB;
        int n0 = blockIdx.x * 32;   // HID
        int k0 = blockIdx.y * 32;   // EMB
#pragma unroll
        for (int i = 0; i < 4; i++)
            tile[r + i * 8][c] = src[(size_t)(k0 + r + i * 8) * HID + n0 + c];
        __syncthreads();
#pragma unroll
        for (int i = 0; i < 4; i++)
            dst[(size_t)(n0 + r + i * 8) * EMB + k0 + c] = __float2half_rn(tile[c][r + i * 8]);
    } else {
        int e = z - 16;
        const float* src = w2 + (size_t)e * HID * EMB;
        __half*      dst = g_w2t + (size_t)e * EMB * HID;
        int k0 = blockIdx.x * 32;   // HID
        int n0 = blockIdx.y * 32;   // EMB
#pragma unroll
        for (int i = 0; i < 4; i++)
            tile[r + i * 8][c] = src[(size_t)(k0 + r + i * 8) * EMB + n0 + c];
        __syncthreads();
#pragma unroll
        for (int i = 0; i < 4; i++)
            dst[(size_t)(n0 + r + i * 8) * HID + k0 + c] = __float2half_rn(tile[c][r + i * 8]);
    }
}

// ---------------- GEMM tiling constants --------------------------------------
#define BK   32
#define ASTR 40                      /* halves: 80B rows, ldmatrix conflict-free */
#define F1_AS  (128 * ASTR * 2)      /* 10240 B */
#define F1_BS  (64 * ASTR * 2)       /* 5120 B  */
#define F1_STG (F1_AS + 2 * F1_BS)   /* 20480 B */
#define F1_SMEM (3 * F1_STG)         /* 61440 B */
#define F2_AS  (128 * ASTR * 2)
#define F2_BS  (128 * ASTR * 2)
#define F2_STG (F2_AS + F2_BS)       /* 20480 B */
#define F2_SMEM (3 * F2_STG)         /* 61440 B */

// ---------------- kernel 3: ffn1 fp16 GEMM + SwiGLU --------------------------
// CTA: 128 pairs x 64 hid cols, both w1 & w3. 3-stage cp.async, ldmatrix frags.
__global__ void __launch_bounds__(256, 2) ffn1_kernel() {
    extern __shared__ __align__(16) char smem[];

    int e = blockIdx.z, nt = blockIdx.y, mt = blockIdx.x;
    int pbeg = g_offsets[e], pend = g_offsets[e + 1];
    int m0 = pbeg + mt * 128;
    if (m0 >= pend) return;
    int mcnt = pend - m0; if (mcnt > 128) mcnt = 128;

    int tid = threadIdx.x;
    int warp = tid >> 5, lane = tid & 31;
    int wm = warp & 3, wn = warp >> 2;     // 4x2 warps, warp tile 32x32 (x2 outputs)
    int gid = lane >> 2, tig = lane & 3;

    int  arow = tid >> 1, aseg = tid & 1;
    bool av   = arow < mcnt;
    int  atok = av ? g_pair_token[m0 + arow] : 0;
    const __half* asrc = g_rx + (size_t)atok * EMB + aseg * 16;
    uint32_t apb = av ? 16u : 0u;

    int brow = tid >> 2, bseg = tid & 3;
    const __half* b1b = g_w1t + ((size_t)e * HID + (size_t)nt * 64 + brow) * EMB + bseg * 8;
    const __half* b3b = g_w3t + ((size_t)e * HID + (size_t)nt * 64 + brow) * EMB + bseg * 8;

    float ch[2][4][4], cg[2][4][4];
#pragma unroll
    for (int a = 0; a < 2; a++)
#pragma unroll
        for (int b = 0; b < 4; b++)
#pragma unroll
            for (int c = 0; c < 4; c++) { ch[a][b][c] = 0.f; cg[a][b][c] = 0.f; }

    // ldmatrix per-lane byte offsets
    uint32_t sbase = (uint32_t)__cvta_generic_to_shared(smem);
    int l16 = lane & 15, lkq = (lane >> 4) * 8;
    uint32_t aoff0 = ((wm * 32 + l16) * ASTR + lkq) * 2;
    uint32_t aoff1 = aoff0 + 16 * ASTR * 2;
    int l8 = lane & 7, q = lane >> 3;
    uint32_t boff0 = ((wn * 32 + (q >> 1) * 8 + l8) * ASTR + (q & 1) * 8) * 2;
    uint32_t boff1 = boff0 + 16 * ASTR * 2;

    auto LOAD = [&](int s, int k0) {
        char* A  = smem + s * F1_STG;
        char* B1 = A + F1_AS;
        char* B3 = B1 + F1_BS;
        cpa(A + (arow * ASTR + aseg * 16) * 2,       asrc + k0,     apb);
        cpa(A + (arow * ASTR + aseg * 16 + 8) * 2,   asrc + k0 + 8, apb);
        cpa(B1 + (brow * ASTR + bseg * 8) * 2, b1b + k0, 16);
        cpa(B3 + (brow * ASTR + bseg * 8) * 2, b3b + k0, 16);
        CP_COMMIT;
    };

    LOAD(0, 0);
    LOAD(1, BK);

    const int NIT = EMB / BK;
    for (int it = 0; it < NIT; ++it) {
        int cur = it - (it / 3) * 3;
        if (it == NIT - 1) { CP_WAIT0; } else { CP_WAIT1; }
        __syncthreads();
        if (it + 2 < NIT) {
            int nxt = cur + 2; if (nxt >= 3) nxt -= 3;
            LOAD(nxt, (it + 2) * BK);
        }

        uint32_t sA  = sbase + cur * F1_STG;
        uint32_t sB1 = sA + F1_AS;
        uint32_t sB3 = sB1 + F1_BS;
#pragma unroll
        for (int kk = 0; kk < BK; kk += 16) {
            uint32_t a[2][4], b1r[8], b3r[8];
            ldsm4(a[0][0], a[0][1], a[0][2], a[0][3], sA + aoff0 + kk * 2);
            ldsm4(a[1][0], a[1][1], a[1][2], a[1][3], sA + aoff1 + kk * 2);
            ldsm4(b1r[0], b1r[1], b1r[2], b1r[3], sB1 + boff0 + kk * 2);
            ldsm4(b1r[4], b1r[5], b1r[6], b1r[7], sB1 + boff1 + kk * 2);
            ldsm4(b3r[0], b3r[1], b3r[2], b3r[3], sB3 + boff0 + kk * 2);
            ldsm4(b3r[4], b3r[5], b3r[6], b3r[7], sB3 + boff1 + kk * 2);
#pragma unroll
            for (int ni = 0; ni < 4; ni++) {
                int bi = (ni >> 1) * 4 + (ni & 1) * 2;
#pragma unroll
                for (int mi = 0; mi < 2; mi++) {
                    mma_f16(ch[mi][ni], a[mi], b1r[bi], b1r[bi + 1]);
                    mma_f16(cg[mi][ni], a[mi], b3r[bi], b3r[bi + 1]);
                }
            }
        }
    }

    // epilogue: silu(h)*g -> fp16 hbuf (half2 stores)
#pragma unroll
    for (int mi = 0; mi < 2; mi++) {
        int r0 = wm * 32 + mi * 16 + gid;
#pragma unroll
        for (int ni = 0; ni < 4; ni++) {
            int colg = nt * 64 + wn * 32 + ni * 8 + tig * 2;
            if (r0 < mcnt) {
                float h0 = ch[mi][ni][0], g0 = cg[mi][ni][0];
                float h1 = ch[mi][ni][1], g1 = cg[mi][ni][1];
                __half2 v = __floats2half2_rn((h0 / (1.f + expf(-h0))) * g0,
                                              (h1 / (1.f + expf(-h1))) * g1);
                *(__half2*)&g_hbuf[(size_t)(m0 + r0) * HID + colg] = v;
            }
            if (r0 + 8 < mcnt) {
                float h0 = ch[mi][ni][2], g0 = cg[mi][ni][2];
                float h1 = ch[mi][ni][3], g1 = cg[mi][ni][3];
                __half2 v = __floats2half2_rn((h0 / (1.f + expf(-h0))) * g0,
                                              (h1 / (1.f + expf(-h1))) * g1);
                *(__half2*)&g_hbuf[(size_t)(m0 + r0 + 8) * HID + colg] = v;
            }
        }
    }
}

// ---------------- kernel 4: ffn2 fp16 GEMM (h @ w2) * gate -------------------
__global__ void __launch_bounds__(256, 2) ffn2_kernel() {
    extern __shared__ __align__(16) char smem[];

    int e = blockIdx.z, nt = blockIdx.y, mt = blockIdx.x;
    int pbeg = g_offsets[e], pend = g_offsets[e + 1];
    int m0 = pbeg + mt * 128;
    if (m0 >= pend) return;
    int mcnt = pend - m0; if (mcnt > 128) mcnt = 128;

    int tid = threadIdx.x;
    int warp = tid >> 5, lane = tid & 31;
    int wm = warp & 3, wn = warp >> 2;     // warp tile 32 rows x 64 cols
    int gid = lane >> 2, tig = lane & 3;

    int  arow = tid >> 1, aseg = tid & 1;
    bool av   = arow < mcnt;
    const __half* asrc = g_hbuf + (size_t)(m0 + (av ? arow : 0)) * HID + aseg * 16;
    uint32_t apb = av ? 16u : 0u;
    const __half* b2b = g_w2t + ((size_t)e * EMB + (size_t)nt * 128 + arow) * HID + aseg * 16;

    float acc[2][8][4];
#pragma unroll
    for (int a = 0; a < 2; a++)
#pragma unroll
        for (int b = 0; b < 8; b++)
#pragma unroll
            for (int c = 0; c < 4; c++) acc[a][b][c] = 0.f;

    uint32_t sbase = (uint32_t)__cvta_generic_to_shared(smem);
    int l16 = lane & 15, lkq = (lane >> 4) * 8;
    uint32_t aoff0 = ((wm * 32 + l16) * ASTR + lkq) * 2;
    uint32_t aoff1 = aoff0 + 16 * ASTR * 2;
    int l8 = lane & 7, q = lane >> 3;
    uint32_t boff[4];
#pragma unroll
    for (int g = 0; g < 4; g++)
        boff[g] = ((wn * 64 + g * 16 + (q >> 1) * 8 + l8) * ASTR + (q & 1) * 8) * 2;

    auto LOAD = [&](int s, int k0) {
        char* A = smem + s * F2_STG;
        char* B = A + F2_AS;
        cpa(A + (arow * ASTR + aseg * 16) * 2,     asrc + k0,     apb);
        cpa(A + (arow * ASTR + aseg * 16 + 8) * 2, asrc + k0 + 8, apb);
        cpa(B + (arow * ASTR + aseg * 16) * 2,     b2b + k0,     16);
        cpa(B + (arow * ASTR + aseg * 16 + 8) * 2, b2b + k0 + 8, 16);
        CP_COMMIT;
    };

    LOAD(0, 0);
    LOAD(1, BK);

    const int NIT = HID / BK;
    for (int it = 0; it < NIT; ++it) {
        int cur = it - (it / 3) * 3;
        if (it == NIT - 1) { CP_WAIT0; } else { CP_WAIT1; }
        __syncthreads();
        if (it + 2 < NIT) {
            int nxt = cur + 2; if (nxt >= 3) nxt -= 3;
            LOAD(nxt, (it + 2) * BK);
        }

        uint32_t sA = sbase + cur * F2_STG;
        uint32_t sB = sA + F2_AS;
#pragma unroll
        for (int kk = 0; kk < BK; kk += 16) {
            uint32_t a[2][4], br[16];
            ldsm4(a[0][0], a[0][1], a[0][2], a[0][3], sA + aoff0 + kk * 2);
            ldsm4(a[1][0], a[1][1], a[1][2], a[1][3], sA + aoff1 + kk * 2);
#pragma unroll
            for (int g = 0; g < 4; g++)
                ldsm4(br[g * 4], br[g * 4 + 1], br[g * 4 + 2], br[g * 4 + 3],
                      sB + boff[g] + kk * 2);
#pragma unroll
            for (int ni = 0; ni < 8; ni++) {
                int bi = (ni >> 1) * 4 + (ni & 1) * 2;
#pragma unroll
                for (int mi = 0; mi < 2; mi++)
                    mma_f16(acc[mi][ni], a[mi], br[bi], br[bi + 1]);
            }
        }
    }

    // epilogue: gate * acc -> per-slot contribution buffer (float2 stores)
#pragma unroll
    for (int mi = 0; mi < 2; mi++) {
        int r0 = wm * 32 + mi * 16 + gid;
        int   t0 = 0, t1 = 0, s0 = 0, s1 = 0;
        float gt0 = 0.f, gt1 = 0.f;
        bool v0 = r0 < mcnt, v1 = (r0 + 8) < mcnt;
        if (v0) { int p = m0 + r0;     t0 = g_pair_token[p]; gt0 = g_pair_gate[p]; s0 = g_pair_slot[p]; }
        if (v1) { int p = m0 + r0 + 8; t1 = g_pair_token[p]; gt1 = g_pair_gate[p]; s1 = g_pair_slot[p]; }
#pragma unroll
        for (int ni = 0; ni < 8; ni++) {
            int colg = nt * 128 + wn * 64 + ni * 8 + tig * 2;
            if (v0) {
                float2 v = make_float2(acc[mi][ni][0] * gt0, acc[mi][ni][1] * gt0);
                *(float2*)&g_contrib[s0][t0][colg] = v;
            }
            if (v1) {
                float2 v = make_float2(acc[mi][ni][2] * gt1, acc[mi][ni][3] * gt1);
                *(float2*)&g_contrib[s1][t1][colg] = v;
            }
        }
    }
}

// ---------------- kernel 5: final reduce -------------------------------------
__global__ void reduce_kernel(float* __restrict__ out) {
    size_t i = (size_t)blockIdx.x * blockDim.x + threadIdx.x;
    size_t n = (size_t)T_TOK * EMB / 4;
    if (i >= n) return;
    const float4* c0 = (const float4*)&g_contrib[0][0][0];
    const float4* c1 = (const float4*)&g_contrib[1][0][0];
    float4 a = c0[i], b = c1[i];
    ((float4*)out)[i] = make_float4(a.x + b.x, a.y + b.y, a.z + b.z, a.w + b.w);
}

// ---------------- launch ------------------------------------------------------
extern "C" void kernel_launch(void* const* d_in, const int* in_sizes, int n_in,
                              void* d_out, int out_size) {
    const float* x  = (const float*)d_in[0];
    const float* wr = (const float*)d_in[1];
    const float* w1 = (const float*)d_in[2];
    const float* w3 = (const float*)d_in[3];
    const float* w2 = (const float*)d_in[4];
    float* out = (float*)d_out;

    cudaFuncSetAttribute(ffn1_kernel, cudaFuncAttributeMaxDynamicSharedMemorySize, F1_SMEM);
    cudaFuncSetAttribute(ffn2_kernel, cudaFuncAttributeMaxDynamicSharedMemorySize, F2_SMEM);

    router_kernel<<<(T_TOK * 32 + 255) / 256, 256>>>(x, wr);           // 0
    offsets_scatter_kernel<<<1, 256>>>();                              // 1
    preround_w_kernel<<<dim3(88, 32, 24), 256>>>(w1, w3, w2);          // 2

    ffn1_kernel<<<dim3(32, HID / 64, NE), 256, F1_SMEM>>>();           // 3  <- ncu capture
    ffn2_kernel<<<dim3(32, EMB / 128, NE), 256, F2_SMEM>>>();          // 4
    reduce_kernel<<<((T_TOK * EMB / 4) + 255) / 256, 256>>>(out);      // 5
}